// round 7
// baseline (speedup 1.0000x reference)
#include <cuda_runtime.h>
#include <cuda_fp16.h>
#include <cstdint>
#include <math.h>

// ---------------------------------------------------------------------------
// Problem constants
// ---------------------------------------------------------------------------
#define NNODES 8192
#define FDIM   16
#define HDIM   64
#define GSEG   256
#define LNEPS  1e-3f
#define ASCALE 8192.0f
#define AINV   (1.0f / 8192.0f)

// GEMM tiling (shared)
#define BM 128
#define NSPLIT 4
#define KSPLIT (NNODES / NSPLIT)   // 2048
#define NSTAGE 4

// GEMM1 (tf32)
#define BK 32
#define LDA 36                      // f32 pitch
#define LDB 36
#define NIT (KSPLIT / BK)           // 64

// GEMM2 (fp16)
#define BK2 64
#define LDH 72                      // half pitch (144 B)
#define NIT2 (KSPLIT / BK2)         // 32
#define ST2A (BM * LDH * 2)         // 18432 B
#define ST2B (64 * LDH * 2)         // 9216 B

// ---------------------------------------------------------------------------
// Device scratch
// ---------------------------------------------------------------------------
__device__ __half dAh[(size_t)NNODES * NNODES];   // A * 8192 in fp16 (128 MB)
__device__ float dY0T[HDIM * NNODES];             // (X@W0)^T f32 tf32-rounded
__device__ __half dY1Th[HDIM * NNODES];           // (h0@W1)^T fp16
__device__ float dZP[NSPLIT * NNODES * HDIM];     // split-K partials
__device__ float dH0[NNODES * HDIM];
__device__ float dG[GSEG * HDIM];
__device__ float dZsum[GSEG];
__device__ float dZnum[GSEG * 3];

// ---------------------------------------------------------------------------
// PTX helpers
// ---------------------------------------------------------------------------
__device__ __forceinline__ uint32_t f2tf(float x) {
    uint32_t r;
    asm("cvt.rna.tf32.f32 %0, %1;" : "=r"(r) : "f"(x));
    return r;
}
__device__ __forceinline__ uint32_t f2tf_bits(uint32_t x) {
    uint32_t r;
    asm("cvt.rna.tf32.f32 %0, %1;" : "=r"(r) : "f"(__uint_as_float(x)));
    return r;
}
__device__ __forceinline__ void cpa16(uint32_t dst, const void *src) {
    asm volatile("cp.async.cg.shared.global [%0], [%1], 16;" ::"r"(dst), "l"(src));
}
__device__ __forceinline__ void cpa_commit() {
    asm volatile("cp.async.commit_group;");
}
__device__ __forceinline__ void cpa_wait2() {
    asm volatile("cp.async.wait_group 2;");
}
__device__ __forceinline__ void ldsm4(uint32_t &r0, uint32_t &r1, uint32_t &r2,
                                      uint32_t &r3, uint32_t addr) {
    asm volatile("ldmatrix.sync.aligned.m8n8.x4.shared.b16 {%0,%1,%2,%3}, [%4];"
                 : "=r"(r0), "=r"(r1), "=r"(r2), "=r"(r3) : "r"(addr));
}
__device__ __forceinline__ void mma_tf32(float c[4], const uint32_t a[4],
                                         const uint32_t b[2]) {
    asm volatile(
        "mma.sync.aligned.m16n8k8.row.col.f32.tf32.tf32.f32 "
        "{%0,%1,%2,%3}, {%4,%5,%6,%7}, {%8,%9}, {%0,%1,%2,%3};"
        : "+f"(c[0]), "+f"(c[1]), "+f"(c[2]), "+f"(c[3])
        : "r"(a[0]), "r"(a[1]), "r"(a[2]), "r"(a[3]), "r"(b[0]), "r"(b[1]));
}
__device__ __forceinline__ void mma_f16(float c[4], const uint32_t a[4],
                                        const uint32_t b[2]) {
    asm volatile(
        "mma.sync.aligned.m16n8k16.row.col.f32.f16.f16.f32 "
        "{%0,%1,%2,%3}, {%4,%5,%6,%7}, {%8,%9}, {%0,%1,%2,%3};"
        : "+f"(c[0]), "+f"(c[1]), "+f"(c[2]), "+f"(c[3])
        : "r"(a[0]), "r"(a[1]), "r"(a[2]), "r"(a[3]), "r"(b[0]), "r"(b[1]));
}

// ---------------------------------------------------------------------------
// zseg: per-graph block; zero dG row; segment max + softmax sums + bary nums
// ---------------------------------------------------------------------------
__global__ void zseg_kernel(const float *__restrict__ X, const int *__restrict__ I) {
    __shared__ int sb[2];
    __shared__ float red[256];
    int g = blockIdx.x, t = threadIdx.x;
    if (t == 0) {
        int a = 0, b = NNODES;
        while (a < b) { int m = (a + b) >> 1; if (I[m] < g) a = m + 1; else b = m; }
        sb[0] = a;
        b = NNODES;
        while (a < b) { int m = (a + b) >> 1; if (I[m] < g + 1) a = m + 1; else b = m; }
        sb[1] = a;
    }
    if (t < HDIM) dG[g * HDIM + t] = 0.f;
    __syncthreads();
    int lo = sb[0], hi = sb[1];

    float zmax = 0.f;
    for (int i = lo + t; i < hi; i += 256)
        zmax = fmaxf(zmax, log1pf(fmaxf(X[i * FDIM], 0.f)));
    red[t] = zmax;
    __syncthreads();
    for (int s = 128; s > 0; s >>= 1) {
        if (t < s) red[t] = fmaxf(red[t], red[t + s]);
        __syncthreads();
    }
    zmax = red[0];
    __syncthreads();

    float se = 0.f, s0 = 0.f, s1 = 0.f, s2 = 0.f;
    for (int i = lo + t; i < hi; i += 256) {
        float z = log1pf(fmaxf(X[i * FDIM], 0.f));
        float w = expf(z - zmax);
        se += w;
        s0 += w * X[i * FDIM + 13];
        s1 += w * X[i * FDIM + 14];
        s2 += w * X[i * FDIM + 15];
    }
    float vals[4] = {se, s0, s1, s2};
#pragma unroll
    for (int q = 0; q < 4; q++) {
        red[t] = vals[q];
        __syncthreads();
        for (int s = 128; s > 0; s >>= 1) {
            if (t < s) red[t] += red[t + s];
            __syncthreads();
        }
        vals[q] = red[0];
        __syncthreads();
    }
    if (t == 0) {
        dZsum[g] = vals[0];
        dZnum[g * 3 + 0] = vals[1];
        dZnum[g * 3 + 1] = vals[2];
        dZnum[g * 3 + 2] = vals[3];
    }
}

// ---------------------------------------------------------------------------
// y0t: Y0T[n][i] = tf32(sum_f X[i][f]*W0[f][n]); smem-staged transposed store
// ---------------------------------------------------------------------------
__global__ void y0t_kernel(const float *__restrict__ X, const float *__restrict__ W0) {
    __shared__ float W0s[FDIM][HDIM];
    __shared__ float ybuf[8][68];
    int lane = threadIdx.x, ty = threadIdx.y;
    int tid = ty * 32 + lane;
#pragma unroll
    for (int j = 0; j < 4; j++) {
        int idx = tid + 256 * j;
        W0s[idx >> 6][idx & 63] = W0[idx];
    }
    __syncthreads();
    int row0 = blockIdx.x * 8;
    int row = row0 + ty;
    float a0 = 0.f, a1 = 0.f;
#pragma unroll
    for (int f = 0; f < FDIM; f++) {
        float xf = X[row * FDIM + f];
        a0 += xf * W0s[f][lane];
        a1 += xf * W0s[f][lane + 32];
    }
    ybuf[ty][lane] = __uint_as_float(f2tf(a0));
    ybuf[ty][lane + 32] = __uint_as_float(f2tf(a1));
    __syncthreads();
#pragma unroll
    for (int k = 0; k < 2; k++) {
        int v = tid + 256 * k;
        int n = v >> 3, r = v & 7;
        dY0T[(size_t)n * NNODES + row0 + r] = ybuf[r][n];
    }
}

// ---------------------------------------------------------------------------
// GEMM1: tf32 tensor-core GEMM + fp16(A*8192) writeout
// ---------------------------------------------------------------------------
__global__ void __launch_bounds__(256, 2)
gemm_tf32(const float *__restrict__ A, const float *__restrict__ BT,
          float *__restrict__ C, __half *__restrict__ Ah) {
    extern __shared__ float smem[];
    float *As = smem;                        // [NSTAGE][BM][LDA]
    float *Bs = smem + NSTAGE * BM * LDA;    // [NSTAGE][64][LDB]

    const int tid = threadIdx.x;
    const int lane = tid & 31, wid = tid >> 5;
    const int wm = wid & 3, wn = wid >> 2;
    const int m0 = blockIdx.x * BM;
    const int kbeg = blockIdx.y * KSPLIT;

    float c[2][4][4] = {};

    const int lr = tid >> 3;
    const int lc = (tid & 7) * 4;
    const float *gA = A + (size_t)(m0 + lr) * NNODES + kbeg + lc;
    const float *gB = BT + (size_t)lr * NNODES + kbeg + lc;
    const uint32_t sA = (uint32_t)__cvta_generic_to_shared(As) + (lr * LDA + lc) * 4;
    const uint32_t sB = (uint32_t)__cvta_generic_to_shared(Bs) + (lr * LDB + lc) * 4;

    const int arow = wm * 32 + (lane & 7) + ((lane >> 3) & 1) * 8;
    const int acoff = ((lane >> 4) & 1) * 4;
    const int brow = wn * 32 + (lane & 7) + ((lane >> 4) & 1) * 8;
    const int bcoff = ((lane >> 3) & 1) * 4;

#define G1_ISSUE(IT)                                                          \
    do {                                                                      \
        int buf = (IT) % NSTAGE;                                              \
        size_t koff = (size_t)(IT) * BK;                                      \
        uint32_t da = sA + buf * (BM * LDA * 4);                              \
        uint32_t db = sB + buf * (64 * LDB * 4);                              \
        _Pragma("unroll") for (int j = 0; j < 4; j++)                         \
            cpa16(da + j * (32 * LDA * 4), gA + koff + (size_t)j * 32 * NNODES); \
        _Pragma("unroll") for (int j = 0; j < 2; j++)                         \
            cpa16(db + j * (32 * LDB * 4), gB + koff + (size_t)j * 32 * NNODES); \
    } while (0)

#define G1_COMPUTE(BUF)                                                       \
    do {                                                                      \
        uint32_t abase = (uint32_t)__cvta_generic_to_shared(As + (BUF) * BM * LDA); \
        uint32_t bbase = (uint32_t)__cvta_generic_to_shared(Bs + (BUF) * 64 * LDB); \
        _Pragma("unroll") for (int ks = 0; ks < 4; ks++) {                    \
            int k0 = ks * 8;                                                  \
            uint32_t a[2][4], b[4][2];                                        \
            _Pragma("unroll") for (int mi = 0; mi < 2; mi++) {                \
                uint32_t addr = abase + ((arow + mi * 16) * LDA + k0 + acoff) * 4; \
                ldsm4(a[mi][0], a[mi][1], a[mi][2], a[mi][3], addr);          \
                _Pragma("unroll") for (int t = 0; t < 4; t++)                 \
                    a[mi][t] = f2tf_bits(a[mi][t]);                           \
            }                                                                 \
            _Pragma("unroll") for (int jp = 0; jp < 2; jp++) {                \
                uint32_t addr = bbase + ((brow + jp * 16) * LDB + k0 + bcoff) * 4; \
                uint32_t r0, r1, r2, r3;                                      \
                ldsm4(r0, r1, r2, r3, addr);                                  \
                b[jp * 2][0] = r0; b[jp * 2][1] = r1;                         \
                b[jp * 2 + 1][0] = r2; b[jp * 2 + 1][1] = r3;                 \
            }                                                                 \
            _Pragma("unroll") for (int mi = 0; mi < 2; mi++)                  \
                _Pragma("unroll") for (int nj = 0; nj < 4; nj++)              \
                    mma_tf32(c[mi][nj], a[mi], b[nj]);                        \
        }                                                                     \
    } while (0)

#pragma unroll
    for (int s = 0; s < NSTAGE - 1; s++) {
        G1_ISSUE(s);
        cpa_commit();
    }

    const int wr = tid >> 1;
    const int wc = (tid & 1) * 16;
    for (int it = 0; it < NIT; ++it) {
        cpa_wait2();
        __syncthreads();
        if (it + NSTAGE - 1 < NIT) G1_ISSUE(it + NSTAGE - 1);
        cpa_commit();
        const int buf = it % NSTAGE;
        G1_COMPUTE(buf);
        {
            const float *ab = As + buf * BM * LDA + wr * LDA + wc;
            __half2 h2[8];
#pragma unroll
            for (int q = 0; q < 8; q++)
                h2[q] = __floats2half2_rn(ab[2 * q] * ASCALE, ab[2 * q + 1] * ASCALE);
            uint4 *dst = (uint4 *)(Ah + (size_t)(m0 + wr) * NNODES + kbeg + it * BK + wc);
            dst[0] = *(uint4 *)&h2[0];
            dst[1] = *(uint4 *)&h2[4];
        }
    }

    float *Cout = C + (size_t)blockIdx.y * NNODES * HDIM;
    int crow = m0 + wm * 32 + (lane >> 2);
    int ccol = wn * 32 + (lane & 3) * 2;
#pragma unroll
    for (int mi = 0; mi < 2; mi++)
#pragma unroll
        for (int nj = 0; nj < 4; nj++) {
            int r = crow + mi * 16, cl = ccol + nj * 8;
            *(float2 *)(Cout + (size_t)r * HDIM + cl) =
                make_float2(c[mi][nj][0], c[mi][nj][1]);
            *(float2 *)(Cout + (size_t)(r + 8) * HDIM + cl) =
                make_float2(c[mi][nj][2], c[mi][nj][3]);
        }
#undef G1_ISSUE
#undef G1_COMPUTE
}

// ---------------------------------------------------------------------------
// GEMM2: fp16 m16n8k16 GEMM
// ---------------------------------------------------------------------------
__global__ void __launch_bounds__(256, 2)
gemm_f16(const __half *__restrict__ Ah, const __half *__restrict__ Bh,
         float *__restrict__ C) {
    extern __shared__ char smc[];
    char *As = smc;
    char *Bs = smc + NSTAGE * ST2A;

    const int tid = threadIdx.x;
    const int lane = tid & 31, wid = tid >> 5;
    const int wm = wid & 3, wn = wid >> 2;
    const int m0 = blockIdx.x * BM;
    const int kbeg = blockIdx.y * KSPLIT;

    float c[2][4][4] = {};

    const int lr = tid >> 3;
    const int lc = (tid & 7) * 8;
    const __half *gA = Ah + (size_t)(m0 + lr) * NNODES + kbeg + lc;
    const __half *gB = Bh + (size_t)lr * NNODES + kbeg + lc;
    const uint32_t sA = (uint32_t)__cvta_generic_to_shared(As) + lr * (LDH * 2) + (tid & 7) * 16;
    const uint32_t sB = (uint32_t)__cvta_generic_to_shared(Bs) + lr * (LDH * 2) + (tid & 7) * 16;

    const int arow = wm * 32 + (lane & 7) + ((lane >> 3) & 1) * 8;
    const int brow_ = wn * 32 + (lane & 7) + ((lane >> 3) & 1) * 8;
    const int kh = ((lane >> 4) & 1) * 8;

#define G2_ISSUE(IT)                                                          \
    do {                                                                      \
        int buf = (IT) % NSTAGE;                                              \
        size_t koff = (size_t)(IT) * BK2;                                     \
        uint32_t da = sA + buf * ST2A;                                        \
        uint32_t db = sB + buf * ST2B;                                        \
        _Pragma("unroll") for (int j = 0; j < 4; j++)                         \
            cpa16(da + j * (32 * LDH * 2), gA + koff + (size_t)j * 32 * NNODES); \
        _Pragma("unroll") for (int j = 0; j < 2; j++)                         \
            cpa16(db + j * (32 * LDH * 2), gB + koff + (size_t)j * 32 * NNODES); \
    } while (0)

#define G2_COMPUTE(BUF)                                                       \
    do {                                                                      \
        uint32_t abase = (uint32_t)__cvta_generic_to_shared(As + (BUF) * ST2A); \
        uint32_t bbase = (uint32_t)__cvta_generic_to_shared(Bs + (BUF) * ST2B); \
        _Pragma("unroll") for (int ks = 0; ks < 4; ks++) {                    \
            int kbase = ks * 16 + kh;                                         \
            uint32_t a[2][4], b[4][2];                                        \
            _Pragma("unroll") for (int mi = 0; mi < 2; mi++) {                \
                uint32_t addr = abase + (arow + mi * 16) * (LDH * 2) + kbase * 2; \
                ldsm4(a[mi][0], a[mi][1], a[mi][2], a[mi][3], addr);          \
            }                                                                 \
            _Pragma("unroll") for (int p = 0; p < 2; p++) {                   \
                uint32_t addr = bbase + (brow_ + p * 16) * (LDH * 2) + kbase * 2; \
                uint32_t r0, r1, r2, r3;                                      \
                ldsm4(r0, r1, r2, r3, addr);                                  \
                b[p * 2][0] = r0; b[p * 2 + 1][0] = r1;                       \
                b[p * 2][1] = r2; b[p * 2 + 1][1] = r3;                       \
            }                                                                 \
            _Pragma("unroll") for (int mi = 0; mi < 2; mi++)                  \
                _Pragma("unroll") for (int nj = 0; nj < 4; nj++)              \
                    mma_f16(c[mi][nj], a[mi], b[nj]);                         \
        }                                                                     \
    } while (0)

#pragma unroll
    for (int s = 0; s < NSTAGE - 1; s++) {
        G2_ISSUE(s);
        cpa_commit();
    }

    for (int it = 0; it < NIT2; ++it) {
        cpa_wait2();
        __syncthreads();
        if (it + NSTAGE - 1 < NIT2) G2_ISSUE(it + NSTAGE - 1);
        cpa_commit();
        G2_COMPUTE(it % NSTAGE);
    }

    float *Cout = C + (size_t)blockIdx.y * NNODES * HDIM;
    int crow = m0 + wm * 32 + (lane >> 2);
    int ccol = wn * 32 + (lane & 3) * 2;
#pragma unroll
    for (int mi = 0; mi < 2; mi++)
#pragma unroll
        for (int nj = 0; nj < 4; nj++) {
            int r = crow + mi * 16, cl = ccol + nj * 8;
            *(float2 *)(Cout + (size_t)r * HDIM + cl) =
                make_float2(c[mi][nj][0], c[mi][nj][1]);
            *(float2 *)(Cout + (size_t)(r + 8) * HDIM + cl) =
                make_float2(c[mi][nj][2], c[mi][nj][3]);
        }
#undef G2_ISSUE
#undef G2_COMPUTE
}

// ---------------------------------------------------------------------------
// mid: h0 = LN(relu(sum ZP + b0)); store h0 f32; Y1T fp16
// block (32,16) = 512 threads, 16 rows/block; float4-packed W matvec
// ---------------------------------------------------------------------------
__global__ void __launch_bounds__(512)
mid_kernel(const float *__restrict__ b0, const float *__restrict__ g0,
           const float *__restrict__ be0, const float *__restrict__ W1) {
    __shared__ float4 W1q[16][64];          // [j/4][n] packed along j
    __shared__ __align__(16) float hrow[16][HDIM];
    __shared__ float ybuf[16][68];
    int lane = threadIdx.x, ty = threadIdx.y;
    int tid = ty * 32 + lane;
    // pack W1 along j: W1q[t][n] = (W1[4t][n], W1[4t+1][n], W1[4t+2][n], W1[4t+3][n])
#pragma unroll
    for (int k = 0; k < 2; k++) {
        int p = tid + 512 * k;               // 0..1023
        int t = p >> 6, n = p & 63;
        W1q[t][n] = make_float4(W1[(4 * t + 0) * HDIM + n], W1[(4 * t + 1) * HDIM + n],
                                W1[(4 * t + 2) * HDIM + n], W1[(4 * t + 3) * HDIM + n]);
    }
    __syncthreads();

    int row0 = blockIdx.x * 16;
    int row = row0 + ty;
    float z0 = b0[lane], z1 = b0[lane + 32];
#pragma unroll
    for (int s = 0; s < NSPLIT; s++) {
        const float *zp = dZP + (size_t)s * NNODES * HDIM + (size_t)row * HDIM;
        z0 += zp[lane];
        z1 += zp[lane + 32];
    }
    z0 = fmaxf(z0, 0.f);
    z1 = fmaxf(z1, 0.f);
    float s = z0 + z1;
#pragma unroll
    for (int o = 16; o > 0; o >>= 1) s += __shfl_xor_sync(0xffffffffu, s, o);
    float m = s * (1.f / 64.f);
    float d0 = z0 - m, d1 = z1 - m;
    float v = d0 * d0 + d1 * d1;
#pragma unroll
    for (int o = 16; o > 0; o >>= 1) v += __shfl_xor_sync(0xffffffffu, v, o);
    float rs = rsqrtf(v * (1.f / 64.f) + LNEPS);
    float h0a = d0 * rs * g0[lane] + be0[lane];
    float h0b = d1 * rs * g0[lane + 32] + be0[lane + 32];
    dH0[(size_t)row * HDIM + lane] = h0a;
    dH0[(size_t)row * HDIM + lane + 32] = h0b;
    hrow[ty][lane] = h0a;
    hrow[ty][lane + 32] = h0b;
    __syncwarp();
    float a0 = 0.f, a1 = 0.f;
    const float4 *h4 = (const float4 *)&hrow[ty][0];
#pragma unroll
    for (int t = 0; t < 16; t++) {
        float4 h = h4[t];
        float4 wa = W1q[t][lane];
        float4 wb = W1q[t][lane + 32];
        a0 += h.x * wa.x + h.y * wa.y + h.z * wa.z + h.w * wa.w;
        a1 += h.x * wb.x + h.y * wb.y + h.z * wb.z + h.w * wb.w;
    }
    ybuf[ty][lane] = a0;
    ybuf[ty][lane + 32] = a1;
    __syncthreads();
#pragma unroll
    for (int k = 0; k < 2; k++) {
        int p = tid + 512 * k;               // 0..1023
        int n = p >> 4, r = p & 15;
        dY1Th[(size_t)n * NNODES + row0 + r] = __float2half_rn(ybuf[r][n]);
    }
}

// ---------------------------------------------------------------------------
// epi2: h = LN(relu(AINV*sum ZP + b1)) + h0; feat/attn matvecs; seg atomics
// block (32,16) = 512 threads; float4-packed Wf/Wa matvecs
// ---------------------------------------------------------------------------
__global__ void __launch_bounds__(512)
epi2_kernel(const int *__restrict__ I, const float *__restrict__ b1,
            const float *__restrict__ g1, const float *__restrict__ be1,
            const float *__restrict__ Wf, const float *__restrict__ bf,
            const float *__restrict__ Wa, const float *__restrict__ ba) {
    __shared__ float4 Wfq[16][64];
    __shared__ float4 Waq[16][64];
    __shared__ __align__(16) float hrow[16][HDIM];
    int lane = threadIdx.x, ty = threadIdx.y;
    int tid = ty * 32 + lane;
#pragma unroll
    for (int k = 0; k < 2; k++) {
        int p = tid + 512 * k;
        int t = p >> 6, n = p & 63;
        Wfq[t][n] = make_float4(Wf[(4 * t + 0) * HDIM + n], Wf[(4 * t + 1) * HDIM + n],
                                Wf[(4 * t + 2) * HDIM + n], Wf[(4 * t + 3) * HDIM + n]);
        Waq[t][n] = make_float4(Wa[(4 * t + 0) * HDIM + n], Wa[(4 * t + 1) * HDIM + n],
                                Wa[(4 * t + 2) * HDIM + n], Wa[(4 * t + 3) * HDIM + n]);
    }
    __syncthreads();

    int row = blockIdx.x * 16 + ty;
    float z0 = 0.f, z1 = 0.f;
#pragma unroll
    for (int s = 0; s < NSPLIT; s++) {
        const float *zp = dZP + (size_t)s * NNODES * HDIM + (size_t)row * HDIM;
        z0 += zp[lane];
        z1 += zp[lane + 32];
    }
    z0 = fmaxf(z0 * AINV + b1[lane], 0.f);
    z1 = fmaxf(z1 * AINV + b1[lane + 32], 0.f);
    float s = z0 + z1;
#pragma unroll
    for (int o = 16; o > 0; o >>= 1) s += __shfl_xor_sync(0xffffffffu, s, o);
    float m = s * (1.f / 64.f);
    float d0 = z0 - m, d1 = z1 - m;
    float v = d0 * d0 + d1 * d1;
#pragma unroll
    for (int o = 16; o > 0; o >>= 1) v += __shfl_xor_sync(0xffffffffu, v, o);
    float rs = rsqrtf(v * (1.f / 64.f) + LNEPS);
    float ha = d0 * rs * g1[lane] + be1[lane] + dH0[(size_t)row * HDIM + lane];
    float hb = d1 * rs * g1[lane + 32] + be1[lane + 32] + dH0[(size_t)row * HDIM + lane + 32];
    hrow[ty][lane] = ha;
    hrow[ty][lane + 32] = hb;
    __syncwarp();

    float f0 = bf[lane], f1 = bf[lane + 32];
    float t0 = ba[lane], t1 = ba[lane + 32];
    const float4 *h4 = (const float4 *)&hrow[ty][0];
#pragma unroll
    for (int t = 0; t < 16; t++) {
        float4 h = h4[t];
        float4 fa = Wfq[t][lane];
        float4 fb = Wfq[t][lane + 32];
        float4 aa = Waq[t][lane];
        float4 ab = Waq[t][lane + 32];
        f0 += h.x * fa.x + h.y * fa.y + h.z * fa.z + h.w * fa.w;
        f1 += h.x * fb.x + h.y * fb.y + h.z * fb.z + h.w * fb.w;
        t0 += h.x * aa.x + h.y * aa.y + h.z * aa.z + h.w * aa.w;
        t1 += h.x * ab.x + h.y * ab.y + h.z * ab.z + h.w * ab.w;
    }
    t0 = 1.f / (1.f + expf(-t0));
    t1 = 1.f / (1.f + expf(-t1));
    int g = I[row];
    atomicAdd(&dG[g * HDIM + lane], f0 * t0);
    atomicAdd(&dG[g * HDIM + lane + 32], f1 * t1);
}

// ---------------------------------------------------------------------------
// final: out[g] = [Gacc[g] | bary[g]] @ Wout + bout
// ---------------------------------------------------------------------------
__global__ void final_kernel(const float *__restrict__ Wout,
                             const float *__restrict__ bout, float *__restrict__ out) {
    int g = blockIdx.x * 64 + threadIdx.x;
    if (g >= GSEG) return;
    float a0 = bout[0], a1 = bout[1], a2 = bout[2];
#pragma unroll
    for (int j = 0; j < HDIM; j++) {
        float v = dG[g * HDIM + j];
        a0 += v * Wout[j * 3 + 0];
        a1 += v * Wout[j * 3 + 1];
        a2 += v * Wout[j * 3 + 2];
    }
    float zs = dZsum[g];
    float inv = zs > 0.f ? 1.f / zs : 0.f;
#pragma unroll
    for (int d = 0; d < 3; d++) {
        float b = dZnum[g * 3 + d] * inv;
        a0 += b * Wout[(HDIM + d) * 3 + 0];
        a1 += b * Wout[(HDIM + d) * 3 + 1];
        a2 += b * Wout[(HDIM + d) * 3 + 2];
    }
    out[g * 3 + 0] = a0;
    out[g * 3 + 1] = a1;
    out[g * 3 + 2] = a2;
}

// ---------------------------------------------------------------------------
// launch
// ---------------------------------------------------------------------------
extern "C" void kernel_launch(void *const *d_in, const int *in_sizes, int n_in,
                              void *d_out, int out_size) {
    const float *X = (const float *)d_in[0];
    const float *A = (const float *)d_in[1];
    const int *I = (const int *)d_in[2];
    const float *W0 = (const float *)d_in[3];
    const float *b0 = (const float *)d_in[4];
    const float *g0 = (const float *)d_in[5];
    const float *be0 = (const float *)d_in[6];
    const float *W1 = (const float *)d_in[7];
    const float *b1 = (const float *)d_in[8];
    const float *g1 = (const float *)d_in[9];
    const float *be1 = (const float *)d_in[10];
    const float *Wf = (const float *)d_in[11];
    const float *bf = (const float *)d_in[12];
    const float *Wa = (const float *)d_in[13];
    const float *ba = (const float *)d_in[14];
    const float *Wout = (const float *)d_in[15];
    const float *bout = (const float *)d_in[16];
    float *out = (float *)d_out;

    float *y0t, *zp;
    __half *ah, *y1th;
    cudaGetSymbolAddress((void **)&y0t, dY0T);
    cudaGetSymbolAddress((void **)&zp, dZP);
    cudaGetSymbolAddress((void **)&ah, dAh);
    cudaGetSymbolAddress((void **)&y1th, dY1Th);

    const int smem1 = NSTAGE * (BM * LDA + 64 * LDB) * 4;  // 110592
    const int smem2 = NSTAGE * (ST2A + ST2B);              // 110592
    cudaFuncSetAttribute(gemm_tf32, cudaFuncAttributeMaxDynamicSharedMemorySize, smem1);
    cudaFuncSetAttribute(gemm_f16, cudaFuncAttributeMaxDynamicSharedMemorySize, smem2);

    zseg_kernel<<<GSEG, 256>>>(X, I);
    y0t_kernel<<<NNODES / 8, dim3(32, 8)>>>(X, W0);
    gemm_tf32<<<dim3(NNODES / BM, NSPLIT), 256, smem1>>>(A, y0t, zp, ah);
    mid_kernel<<<NNODES / 16, dim3(32, 16)>>>(b0, g0, be0, W1);
    gemm_f16<<<dim3(NNODES / BM, NSPLIT), 256, smem2>>>(ah, y1th, zp);
    epi2_kernel<<<NNODES / 16, dim3(32, 16)>>>(I, b1, g1, be1, Wf, bf, Wa, ba);
    final_kernel<<<(GSEG + 63) / 64, 64>>>(Wout, bout, out);
}

// round 8
// speedup vs baseline: 1.0605x; 1.0605x over previous
#include <cuda_runtime.h>
#include <cuda_fp16.h>
#include <cstdint>
#include <math.h>

// ---------------------------------------------------------------------------
// Problem constants
// ---------------------------------------------------------------------------
#define NNODES 8192
#define FDIM   16
#define HDIM   64
#define GSEG   256
#define LNEPS  1e-3f
#define ASCALE 8192.0f
#define AINV   (1.0f / 8192.0f)

// GEMM tiling (fp16, m16n8k16)
#define BM 128
#define NSPLIT 4
#define KSPLIT (NNODES / NSPLIT)   // 2048
#define NSTAGE 4
#define BK2 64
#define LDH 72                      // half pitch (144 B)
#define NIT2 (KSPLIT / BK2)         // 32
#define ST2A (BM * LDH * 2)         // 18432 B
#define ST2B (64 * LDH * 2)         // 9216 B

// ---------------------------------------------------------------------------
// Device scratch
// ---------------------------------------------------------------------------
__device__ __half dAh[(size_t)NNODES * NNODES];   // A * 8192 in fp16 (128 MB)
__device__ __half dY0Th[HDIM * NNODES];           // (X@W0)^T fp16
__device__ __half dY1Th[HDIM * NNODES];           // (h0@W1)^T fp16
__device__ float dZP[NSPLIT * NNODES * HDIM];     // split-K partials
__device__ float dH0[NNODES * HDIM];
__device__ float dG[GSEG * HDIM];
__device__ float dZsum[GSEG];
__device__ float dZnum[GSEG * 3];

// ---------------------------------------------------------------------------
// PTX helpers
// ---------------------------------------------------------------------------
__device__ __forceinline__ void cpa16(uint32_t dst, const void *src) {
    asm volatile("cp.async.cg.shared.global [%0], [%1], 16;" ::"r"(dst), "l"(src));
}
__device__ __forceinline__ void cpa_commit() {
    asm volatile("cp.async.commit_group;");
}
__device__ __forceinline__ void cpa_wait2() {
    asm volatile("cp.async.wait_group 2;");
}
__device__ __forceinline__ void ldsm4(uint32_t &r0, uint32_t &r1, uint32_t &r2,
                                      uint32_t &r3, uint32_t addr) {
    asm volatile("ldmatrix.sync.aligned.m8n8.x4.shared.b16 {%0,%1,%2,%3}, [%4];"
                 : "=r"(r0), "=r"(r1), "=r"(r2), "=r"(r3) : "r"(addr));
}
__device__ __forceinline__ void mma_f16(float c[4], const uint32_t a[4],
                                        const uint32_t b[2]) {
    asm volatile(
        "mma.sync.aligned.m16n8k16.row.col.f32.f16.f16.f32 "
        "{%0,%1,%2,%3}, {%4,%5,%6,%7}, {%8,%9}, {%0,%1,%2,%3};"
        : "+f"(c[0]), "+f"(c[1]), "+f"(c[2]), "+f"(c[3])
        : "r"(a[0]), "r"(a[1]), "r"(a[2]), "r"(a[3]), "r"(b[0]), "r"(b[1]));
}

// ---------------------------------------------------------------------------
// conv: Ah = fp16(A * 8192), pure streaming (float4 in, uint4 out)
// 64M elements; each thread converts 8 f32 -> 8 half per step
// ---------------------------------------------------------------------------
__global__ void __launch_bounds__(256)
conv_kernel(const float *__restrict__ A, __half *__restrict__ Ah) {
    const size_t stride = (size_t)gridDim.x * 256 * 8;
    size_t base = ((size_t)blockIdx.x * 256 + threadIdx.x) * 8;
    const size_t total = (size_t)NNODES * NNODES;
    for (size_t i = base; i < total; i += stride) {
        float4 v0 = *(const float4 *)(A + i);
        float4 v1 = *(const float4 *)(A + i + 4);
        __half2 h[4];
        h[0] = __floats2half2_rn(v0.x * ASCALE, v0.y * ASCALE);
        h[1] = __floats2half2_rn(v0.z * ASCALE, v0.w * ASCALE);
        h[2] = __floats2half2_rn(v1.x * ASCALE, v1.y * ASCALE);
        h[3] = __floats2half2_rn(v1.z * ASCALE, v1.w * ASCALE);
        *(uint4 *)(Ah + i) = *(uint4 *)h;
    }
}

// ---------------------------------------------------------------------------
// y0t: Y0Th[n][i] = fp16(sum_f X[i][f]*W0[f][n]); smem-staged transposed store
// ---------------------------------------------------------------------------
__global__ void y0t_kernel(const float *__restrict__ X, const float *__restrict__ W0) {
    __shared__ float W0s[FDIM][HDIM];
    __shared__ float ybuf[8][68];
    int lane = threadIdx.x, ty = threadIdx.y;
    int tid = ty * 32 + lane;
#pragma unroll
    for (int j = 0; j < 4; j++) {
        int idx = tid + 256 * j;
        W0s[idx >> 6][idx & 63] = W0[idx];
    }
    __syncthreads();
    int row0 = blockIdx.x * 8;
    int row = row0 + ty;
    float a0 = 0.f, a1 = 0.f;
#pragma unroll
    for (int f = 0; f < FDIM; f++) {
        float xf = X[row * FDIM + f];
        a0 += xf * W0s[f][lane];
        a1 += xf * W0s[f][lane + 32];
    }
    ybuf[ty][lane] = a0;
    ybuf[ty][lane + 32] = a1;
    __syncthreads();
#pragma unroll
    for (int k = 0; k < 2; k++) {
        int v = tid + 256 * k;
        int n = v >> 3, r = v & 7;
        dY0Th[(size_t)n * NNODES + row0 + r] = __float2half_rn(ybuf[r][n]);
    }
}

// ---------------------------------------------------------------------------
// GEMM (fp16 m16n8k16): dZP[y] = Ah[:, y*2048...] @ Bh^T   (scaled x8192)
// ---------------------------------------------------------------------------
__global__ void __launch_bounds__(256, 2)
gemm_f16(const __half *__restrict__ Ah, const __half *__restrict__ Bh,
         float *__restrict__ C) {
    extern __shared__ char smc[];
    char *As = smc;                       // [NSTAGE][BM][LDH halfs]
    char *Bs = smc + NSTAGE * ST2A;       // [NSTAGE][64][LDH halfs]

    const int tid = threadIdx.x;
    const int lane = tid & 31, wid = tid >> 5;
    const int wm = wid & 3, wn = wid >> 2;
    const int m0 = blockIdx.x * BM;
    const int kbeg = blockIdx.y * KSPLIT;

    float c[2][4][4] = {};

    const int lr = tid >> 3;
    const int lc = (tid & 7) * 8;
    const __half *gA = Ah + (size_t)(m0 + lr) * NNODES + kbeg + lc;
    const __half *gB = Bh + (size_t)lr * NNODES + kbeg + lc;
    const uint32_t sA = (uint32_t)__cvta_generic_to_shared(As) + lr * (LDH * 2) + (tid & 7) * 16;
    const uint32_t sB = (uint32_t)__cvta_generic_to_shared(Bs) + lr * (LDH * 2) + (tid & 7) * 16;

    const int arow = wm * 32 + (lane & 7) + ((lane >> 3) & 1) * 8;
    const int brow_ = wn * 32 + (lane & 7) + ((lane >> 3) & 1) * 8;
    const int kh = ((lane >> 4) & 1) * 8;

#define G2_ISSUE(IT)                                                          \
    do {                                                                      \
        int buf = (IT) % NSTAGE;                                              \
        size_t koff = (size_t)(IT) * BK2;                                     \
        uint32_t da = sA + buf * ST2A;                                        \
        uint32_t db = sB + buf * ST2B;                                        \
        _Pragma("unroll") for (int j = 0; j < 4; j++)                         \
            cpa16(da + j * (32 * LDH * 2), gA + koff + (size_t)j * 32 * NNODES); \
        _Pragma("unroll") for (int j = 0; j < 2; j++)                         \
            cpa16(db + j * (32 * LDH * 2), gB + koff + (size_t)j * 32 * NNODES); \
    } while (0)

#define G2_COMPUTE(BUF)                                                       \
    do {                                                                      \
        uint32_t abase = (uint32_t)__cvta_generic_to_shared(As + (BUF) * ST2A); \
        uint32_t bbase = (uint32_t)__cvta_generic_to_shared(Bs + (BUF) * ST2B); \
        _Pragma("unroll") for (int ks = 0; ks < 4; ks++) {                    \
            int kbase = ks * 16 + kh;                                         \
            uint32_t a[2][4], b[4][2];                                        \
            _Pragma("unroll") for (int mi = 0; mi < 2; mi++) {                \
                uint32_t addr = abase + (arow + mi * 16) * (LDH * 2) + kbase * 2; \
                ldsm4(a[mi][0], a[mi][1], a[mi][2], a[mi][3], addr);          \
            }                                                                 \
            _Pragma("unroll") for (int p = 0; p < 2; p++) {                   \
                uint32_t addr = bbase + (brow_ + p * 16) * (LDH * 2) + kbase * 2; \
                uint32_t r0, r1, r2, r3;                                      \
                ldsm4(r0, r1, r2, r3, addr);                                  \
                b[p * 2][0] = r0; b[p * 2 + 1][0] = r1;                       \
                b[p * 2][1] = r2; b[p * 2 + 1][1] = r3;                       \
            }                                                                 \
            _Pragma("unroll") for (int mi = 0; mi < 2; mi++)                  \
                _Pragma("unroll") for (int nj = 0; nj < 4; nj++)              \
                    mma_f16(c[mi][nj], a[mi], b[nj]);                         \
        }                                                                     \
    } while (0)

#pragma unroll
    for (int s = 0; s < NSTAGE - 1; s++) {
        G2_ISSUE(s);
        cpa_commit();
    }

    for (int it = 0; it < NIT2; ++it) {
        cpa_wait2();
        __syncthreads();
        if (it + NSTAGE - 1 < NIT2) G2_ISSUE(it + NSTAGE - 1);
        cpa_commit();
        G2_COMPUTE(it % NSTAGE);
    }

    float *Cout = C + (size_t)blockIdx.y * NNODES * HDIM;
    int crow = m0 + wm * 32 + (lane >> 2);
    int ccol = wn * 32 + (lane & 3) * 2;
#pragma unroll
    for (int mi = 0; mi < 2; mi++)
#pragma unroll
        for (int nj = 0; nj < 4; nj++) {
            int r = crow + mi * 16, cl = ccol + nj * 8;
            *(float2 *)(Cout + (size_t)r * HDIM + cl) =
                make_float2(c[mi][nj][0], c[mi][nj][1]);
            *(float2 *)(Cout + (size_t)(r + 8) * HDIM + cl) =
                make_float2(c[mi][nj][2], c[mi][nj][3]);
        }
#undef G2_ISSUE
#undef G2_COMPUTE
}

// ---------------------------------------------------------------------------
// zseg: per-graph block; zero dG row; segment max + softmax sums + bary nums
// ---------------------------------------------------------------------------
__global__ void zseg_kernel(const float *__restrict__ X, const int *__restrict__ I) {
    __shared__ int sb[2];
    __shared__ float red[256];
    int g = blockIdx.x, t = threadIdx.x;
    if (t == 0) {
        int a = 0, b = NNODES;
        while (a < b) { int m = (a + b) >> 1; if (I[m] < g) a = m + 1; else b = m; }
        sb[0] = a;
        b = NNODES;
        while (a < b) { int m = (a + b) >> 1; if (I[m] < g + 1) a = m + 1; else b = m; }
        sb[1] = a;
    }
    if (t < HDIM) dG[g * HDIM + t] = 0.f;
    __syncthreads();
    int lo = sb[0], hi = sb[1];

    float zmax = 0.f;
    for (int i = lo + t; i < hi; i += 256)
        zmax = fmaxf(zmax, log1pf(fmaxf(X[i * FDIM], 0.f)));
    red[t] = zmax;
    __syncthreads();
    for (int s = 128; s > 0; s >>= 1) {
        if (t < s) red[t] = fmaxf(red[t], red[t + s]);
        __syncthreads();
    }
    zmax = red[0];
    __syncthreads();

    float se = 0.f, s0 = 0.f, s1 = 0.f, s2 = 0.f;
    for (int i = lo + t; i < hi; i += 256) {
        float z = log1pf(fmaxf(X[i * FDIM], 0.f));
        float w = expf(z - zmax);
        se += w;
        s0 += w * X[i * FDIM + 13];
        s1 += w * X[i * FDIM + 14];
        s2 += w * X[i * FDIM + 15];
    }
    float vals[4] = {se, s0, s1, s2};
#pragma unroll
    for (int q = 0; q < 4; q++) {
        red[t] = vals[q];
        __syncthreads();
        for (int s = 128; s > 0; s >>= 1) {
            if (t < s) red[t] += red[t + s];
            __syncthreads();
        }
        vals[q] = red[0];
        __syncthreads();
    }
    if (t == 0) {
        dZsum[g] = vals[0];
        dZnum[g * 3 + 0] = vals[1];
        dZnum[g * 3 + 1] = vals[2];
        dZnum[g * 3 + 2] = vals[3];
    }
}

// ---------------------------------------------------------------------------
// mid: h0 = LN(relu(AINV*sum ZP + b0)); store h0 f32; Y1Th fp16
// ---------------------------------------------------------------------------
__global__ void __launch_bounds__(512)
mid_kernel(const float *__restrict__ b0, const float *__restrict__ g0,
           const float *__restrict__ be0, const float *__restrict__ W1) {
    __shared__ float4 W1q[16][64];
    __shared__ __align__(16) float hrow[16][HDIM];
    __shared__ float ybuf[16][68];
    int lane = threadIdx.x, ty = threadIdx.y;
    int tid = ty * 32 + lane;
#pragma unroll
    for (int k = 0; k < 2; k++) {
        int p = tid + 512 * k;
        int t = p >> 6, n = p & 63;
        W1q[t][n] = make_float4(W1[(4 * t + 0) * HDIM + n], W1[(4 * t + 1) * HDIM + n],
                                W1[(4 * t + 2) * HDIM + n], W1[(4 * t + 3) * HDIM + n]);
    }
    __syncthreads();

    int row0 = blockIdx.x * 16;
    int row = row0 + ty;
    float z0 = 0.f, z1 = 0.f;
#pragma unroll
    for (int s = 0; s < NSPLIT; s++) {
        const float *zp = dZP + (size_t)s * NNODES * HDIM + (size_t)row * HDIM;
        z0 += zp[lane];
        z1 += zp[lane + 32];
    }
    z0 = fmaxf(z0 * AINV + b0[lane], 0.f);
    z1 = fmaxf(z1 * AINV + b0[lane + 32], 0.f);
    float s = z0 + z1;
#pragma unroll
    for (int o = 16; o > 0; o >>= 1) s += __shfl_xor_sync(0xffffffffu, s, o);
    float m = s * (1.f / 64.f);
    float d0 = z0 - m, d1 = z1 - m;
    float v = d0 * d0 + d1 * d1;
#pragma unroll
    for (int o = 16; o > 0; o >>= 1) v += __shfl_xor_sync(0xffffffffu, v, o);
    float rs = rsqrtf(v * (1.f / 64.f) + LNEPS);
    float h0a = d0 * rs * g0[lane] + be0[lane];
    float h0b = d1 * rs * g0[lane + 32] + be0[lane + 32];
    dH0[(size_t)row * HDIM + lane] = h0a;
    dH0[(size_t)row * HDIM + lane + 32] = h0b;
    hrow[ty][lane] = h0a;
    hrow[ty][lane + 32] = h0b;
    __syncwarp();
    float a0 = 0.f, a1 = 0.f;
    const float4 *h4 = (const float4 *)&hrow[ty][0];
#pragma unroll
    for (int t = 0; t < 16; t++) {
        float4 h = h4[t];
        float4 wa = W1q[t][lane];
        float4 wb = W1q[t][lane + 32];
        a0 += h.x * wa.x + h.y * wa.y + h.z * wa.z + h.w * wa.w;
        a1 += h.x * wb.x + h.y * wb.y + h.z * wb.z + h.w * wb.w;
    }
    ybuf[ty][lane] = a0;
    ybuf[ty][lane + 32] = a1;
    __syncthreads();
#pragma unroll
    for (int k = 0; k < 2; k++) {
        int p = tid + 512 * k;
        int n = p >> 4, r = p & 15;
        dY1Th[(size_t)n * NNODES + row0 + r] = __float2half_rn(ybuf[r][n]);
    }
}

// ---------------------------------------------------------------------------
// epi2: h = LN(relu(AINV*sum ZP + b1)) + h0; feat/attn matvecs; seg atomics
// ---------------------------------------------------------------------------
__global__ void __launch_bounds__(512)
epi2_kernel(const int *__restrict__ I, const float *__restrict__ b1,
            const float *__restrict__ g1, const float *__restrict__ be1,
            const float *__restrict__ Wf, const float *__restrict__ bf,
            const float *__restrict__ Wa, const float *__restrict__ ba) {
    __shared__ float4 Wfq[16][64];
    __shared__ float4 Waq[16][64];
    __shared__ __align__(16) float hrow[16][HDIM];
    int lane = threadIdx.x, ty = threadIdx.y;
    int tid = ty * 32 + lane;
#pragma unroll
    for (int k = 0; k < 2; k++) {
        int p = tid + 512 * k;
        int t = p >> 6, n = p & 63;
        Wfq[t][n] = make_float4(Wf[(4 * t + 0) * HDIM + n], Wf[(4 * t + 1) * HDIM + n],
                                Wf[(4 * t + 2) * HDIM + n], Wf[(4 * t + 3) * HDIM + n]);
        Waq[t][n] = make_float4(Wa[(4 * t + 0) * HDIM + n], Wa[(4 * t + 1) * HDIM + n],
                                Wa[(4 * t + 2) * HDIM + n], Wa[(4 * t + 3) * HDIM + n]);
    }
    __syncthreads();

    int row = blockIdx.x * 16 + ty;
    float z0 = 0.f, z1 = 0.f;
#pragma unroll
    for (int s = 0; s < NSPLIT; s++) {
        const float *zp = dZP + (size_t)s * NNODES * HDIM + (size_t)row * HDIM;
        z0 += zp[lane];
        z1 += zp[lane + 32];
    }
    z0 = fmaxf(z0 * AINV + b1[lane], 0.f);
    z1 = fmaxf(z1 * AINV + b1[lane + 32], 0.f);
    float s = z0 + z1;
#pragma unroll
    for (int o = 16; o > 0; o >>= 1) s += __shfl_xor_sync(0xffffffffu, s, o);
    float m = s * (1.f / 64.f);
    float d0 = z0 - m, d1 = z1 - m;
    float v = d0 * d0 + d1 * d1;
#pragma unroll
    for (int o = 16; o > 0; o >>= 1) v += __shfl_xor_sync(0xffffffffu, v, o);
    float rs = rsqrtf(v * (1.f / 64.f) + LNEPS);
    float ha = d0 * rs * g1[lane] + be1[lane] + dH0[(size_t)row * HDIM + lane];
    float hb = d1 * rs * g1[lane + 32] + be1[lane + 32] + dH0[(size_t)row * HDIM + lane + 32];
    hrow[ty][lane] = ha;
    hrow[ty][lane + 32] = hb;
    __syncwarp();

    float f0 = bf[lane], f1 = bf[lane + 32];
    float t0 = ba[lane], t1 = ba[lane + 32];
    const float4 *h4 = (const float4 *)&hrow[ty][0];
#pragma unroll
    for (int t = 0; t < 16; t++) {
        float4 h = h4[t];
        float4 fa = Wfq[t][lane];
        float4 fb = Wfq[t][lane + 32];
        float4 aa = Waq[t][lane];
        float4 ab = Waq[t][lane + 32];
        f0 += h.x * fa.x + h.y * fa.y + h.z * fa.z + h.w * fa.w;
        f1 += h.x * fb.x + h.y * fb.y + h.z * fb.z + h.w * fb.w;
        t0 += h.x * aa.x + h.y * aa.y + h.z * aa.z + h.w * aa.w;
        t1 += h.x * ab.x + h.y * ab.y + h.z * ab.z + h.w * ab.w;
    }
    t0 = 1.f / (1.f + expf(-t0));
    t1 = 1.f / (1.f + expf(-t1));
    int g = I[row];
    atomicAdd(&dG[g * HDIM + lane], f0 * t0);
    atomicAdd(&dG[g * HDIM + lane + 32], f1 * t1);
}

// ---------------------------------------------------------------------------
// final: out[g] = [Gacc[g] | bary[g]] @ Wout + bout
// ---------------------------------------------------------------------------
__global__ void final_kernel(const float *__restrict__ Wout,
                             const float *__restrict__ bout, float *__restrict__ out) {
    int g = blockIdx.x * 64 + threadIdx.x;
    if (g >= GSEG) return;
    float a0 = bout[0], a1 = bout[1], a2 = bout[2];
#pragma unroll
    for (int j = 0; j < HDIM; j++) {
        float v = dG[g * HDIM + j];
        a0 += v * Wout[j * 3 + 0];
        a1 += v * Wout[j * 3 + 1];
        a2 += v * Wout[j * 3 + 2];
    }
    float zs = dZsum[g];
    float inv = zs > 0.f ? 1.f / zs : 0.f;
#pragma unroll
    for (int d = 0; d < 3; d++) {
        float b = dZnum[g * 3 + d] * inv;
        a0 += b * Wout[(HDIM + d) * 3 + 0];
        a1 += b * Wout[(HDIM + d) * 3 + 1];
        a2 += b * Wout[(HDIM + d) * 3 + 2];
    }
    out[g * 3 + 0] = a0;
    out[g * 3 + 1] = a1;
    out[g * 3 + 2] = a2;
}

// ---------------------------------------------------------------------------
// launch
// ---------------------------------------------------------------------------
extern "C" void kernel_launch(void *const *d_in, const int *in_sizes, int n_in,
                              void *d_out, int out_size) {
    const float *X = (const float *)d_in[0];
    const float *A = (const float *)d_in[1];
    const int *I = (const int *)d_in[2];
    const float *W0 = (const float *)d_in[3];
    const float *b0 = (const float *)d_in[4];
    const float *g0 = (const float *)d_in[5];
    const float *be0 = (const float *)d_in[6];
    const float *W1 = (const float *)d_in[7];
    const float *b1 = (const float *)d_in[8];
    const float *g1 = (const float *)d_in[9];
    const float *be1 = (const float *)d_in[10];
    const float *Wf = (const float *)d_in[11];
    const float *bf = (const float *)d_in[12];
    const float *Wa = (const float *)d_in[13];
    const float *ba = (const float *)d_in[14];
    const float *Wout = (const float *)d_in[15];
    const float *bout = (const float *)d_in[16];
    float *out = (float *)d_out;

    float *zp;
    __half *ah, *y0th, *y1th;
    cudaGetSymbolAddress((void **)&zp, dZP);
    cudaGetSymbolAddress((void **)&ah, dAh);
    cudaGetSymbolAddress((void **)&y0th, dY0Th);
    cudaGetSymbolAddress((void **)&y1th, dY1Th);

    const int smem2 = NSTAGE * (ST2A + ST2B);  // 110592
    cudaFuncSetAttribute(gemm_f16, cudaFuncAttributeMaxDynamicSharedMemorySize, smem2);

    conv_kernel<<<2048, 256>>>(A, ah);
    y0t_kernel<<<NNODES / 8, dim3(32, 8)>>>(X, W0);
    gemm_f16<<<dim3(NNODES / BM, NSPLIT), 256, smem2>>>(ah, y0th, zp);
    mid_kernel<<<NNODES / 16, dim3(32, 16)>>>(b0, g0, be0, W1);
    gemm_f16<<<dim3(NNODES / BM, NSPLIT), 256, smem2>>>(ah, y1th, zp);
    zseg_kernel<<<GSEG, 256>>>(X, I);
    epi2_kernel<<<NNODES / 16, dim3(32, 16)>>>(I, b1, g1, be1, Wf, bf, Wa, ba);
    final_kernel<<<(GSEG + 63) / 64, 64>>>(Wout, bout, out);
}